// round 11
// baseline (speedup 1.0000x reference)
#include <cuda_runtime.h>

// MaxLocaldist: per output pixel, max pairwise L2 distance among the 9 RGB
// pixels of the 3x3 neighborhood. Input (32,3,224,224) f32 NCHW.
// Output (32,1,224,224) f32, 1-pixel zero border.
//
// Column-pair decomposition + temporal d2 caching (12 evals/output, shared
// across lanes via shfls), processing TWO output rows per iteration:
// 4-row rolling register window, carried state across iterations is only
// 2 rows + 9 cache entries (27 regs). The two halves of each iteration are
// independent dependency chains -> ~2x per-warp ILP at the same occupancy
// (issue was 62% with nothing saturated: latency-bound, not slot-bound).

#define HD 224
#define WD 224
#define HWD (HD * WD)
#define FULLMASK 0xffffffffu

__device__ __forceinline__ float d2s(const float a[3], const float b[3]) {
    const float dx = a[0] - b[0];
    const float dy = a[1] - b[1];
    const float dz = a[2] - b[2];
    return fmaf(dx, dx, fmaf(dy, dy, dz * dz));
}

__device__ __forceinline__ float max9(float e0, float e1, float e2, float e3,
                                      float e4, float e5, float e6, float e7,
                                      float e8) {
    // balanced tree, depth 4
    const float m01 = fmaxf(e0, e1), m23 = fmaxf(e2, e3);
    const float m45 = fmaxf(e4, e5), m67 = fmaxf(e6, e7);
    return fmaxf(fmaxf(fmaxf(m01, m23), fmaxf(m45, m67)), e8);
}

__global__ __launch_bounds__(256, 4) void maxlocaldist_kernel(
    const float* __restrict__ x, float* __restrict__ out)
{
    const int lane = threadIdx.x & 31;
    const int wgrp = threadIdx.x >> 5;          // 0..7: 30 output cols per warp
    const int b    = blockIdx.z;
    const int h0   = blockIdx.y * 8;            // 8 output rows per block
    const int c0   = wgrp * 30 + lane;

    const float* xb = x + (long)b * 3 * HWD;

    int col[3];
#pragma unroll
    for (int j = 0; j < 3; j++) col[j] = min(c0 + j, WD - 1);

    // 4-slot rolling window: pt[slot][colj][ch]; slot = relative-row & 3
    float pt[4][3][3];
    // caches indexed by slot
    float D01[4][4], D02[4][4], sd1[4], sd2[4];

    // ---- prologue: rows h0-1 (slot 0, clamped) and h0 (slot 1)
#pragma unroll
    for (int s = 0; s < 2; s++) {
        const int r = max(h0 - 1 + s, 0);
#pragma unroll
        for (int ch = 0; ch < 3; ch++)
#pragma unroll
            for (int j = 0; j < 3; j++)
                pt[s][j][ch] = __ldg(xb + ch * HWD + r * WD + col[j]);
    }
    D01[0][0] = d2s(pt[0][0], pt[0][1]);
    D01[0][1] = d2s(pt[0][0], pt[1][1]);
    D01[1][0] = d2s(pt[1][0], pt[0][1]);
    D01[1][1] = d2s(pt[1][0], pt[1][1]);
    D02[0][0] = d2s(pt[0][0], pt[0][2]);
    D02[0][1] = d2s(pt[0][0], pt[1][2]);
    D02[1][0] = d2s(pt[1][0], pt[0][2]);
    D02[1][1] = d2s(pt[1][0], pt[1][2]);
    sd1[0]    = d2s(pt[0][0], pt[1][0]);

    const int  w_out   = c0 + 1;
    const bool wvalid  = (lane < 30) && (w_out <= WD - 1);
    const bool zerocol = (wgrp == 0) && (lane == 31);

#pragma unroll
    for (int t = 0; t < 4; t++) {
        const int ha = h0 + 2 * t;          // first output row this iter
        const int hb = ha + 1;
        const int sA = (2 * t)     & 3;     // row ha-1
        const int sB = (2 * t + 1) & 3;     // row ha
        const int sC = (2 * t + 2) & 3;     // row ha+1 = hb
        const int sD = (2 * t + 3) & 3;     // row ha+2 = hb+1

        // ---- load row C (= hb, always <= 223)
#pragma unroll
        for (int ch = 0; ch < 3; ch++)
#pragma unroll
            for (int j = 0; j < 3; j++)
                pt[sC][j][ch] = __ldg(xb + ch * HWD + hb * WD + col[j]);

        // refresh entries involving row C
        D01[sC][sA] = d2s(pt[sC][0], pt[sA][1]);
        D01[sC][sB] = d2s(pt[sC][0], pt[sB][1]);
        D01[sC][sC] = d2s(pt[sC][0], pt[sC][1]);
        D01[sA][sC] = d2s(pt[sA][0], pt[sC][1]);
        D01[sB][sC] = d2s(pt[sB][0], pt[sC][1]);
        D02[sC][sA] = d2s(pt[sC][0], pt[sA][2]);
        D02[sC][sB] = d2s(pt[sC][0], pt[sB][2]);
        D02[sC][sC] = d2s(pt[sC][0], pt[sC][2]);
        D02[sA][sC] = d2s(pt[sA][0], pt[sC][2]);
        D02[sB][sC] = d2s(pt[sB][0], pt[sC][2]);
        sd2[sA]     = d2s(pt[sA][0], pt[sC][0]);
        sd1[sB]     = d2s(pt[sB][0], pt[sC][0]);

        // ---- load row D (= hb+1, clamp only at the bottom edge)
        const int rD = min(ha + 2, HD - 1);
#pragma unroll
        for (int ch = 0; ch < 3; ch++)
#pragma unroll
            for (int j = 0; j < 3; j++)
                pt[sD][j][ch] = __ldg(xb + ch * HWD + rD * WD + col[j]);

        // ---- output ha (rows sA,sB,sC) — independent of row D
        const float Sa = fmaxf(fmaxf(sd1[sA], sd2[sA]), sd1[sB]);
        const float P01a = max9(D01[sA][sA], D01[sA][sB], D01[sB][sA],
                                D01[sB][sB], D01[sC][sA], D01[sC][sB],
                                D01[sC][sC], D01[sA][sC], D01[sB][sC]);
        const float P02a = max9(D02[sA][sA], D02[sA][sB], D02[sB][sA],
                                D02[sB][sB], D02[sC][sA], D02[sC][sB],
                                D02[sC][sC], D02[sA][sC], D02[sB][sC]);

        const float S1a = __shfl_down_sync(FULLMASK, Sa,   1);
        const float S2a = __shfl_down_sync(FULLMASK, Sa,   2);
        const float Qa  = __shfl_down_sync(FULLMASK, P01a, 1);
        const float ma  = fmaxf(fmaxf(fmaxf(Sa, S1a), fmaxf(S2a, P01a)),
                                fmaxf(Qa, P02a));
        float va;
        asm("sqrt.approx.f32 %0, %1;" : "=f"(va) : "f"(ma));
        {
            const bool border = (ha == 0) || (w_out == WD - 1);
            if (wvalid)
                out[((long)b * HD + ha) * WD + w_out] = border ? 0.0f : va;
            if (zerocol)
                out[((long)b * HD + ha) * WD] = 0.0f;
        }

        // refresh entries involving row D
        D01[sD][sB] = d2s(pt[sD][0], pt[sB][1]);
        D01[sD][sC] = d2s(pt[sD][0], pt[sC][1]);
        D01[sD][sD] = d2s(pt[sD][0], pt[sD][1]);
        D01[sB][sD] = d2s(pt[sB][0], pt[sD][1]);
        D01[sC][sD] = d2s(pt[sC][0], pt[sD][1]);
        D02[sD][sB] = d2s(pt[sD][0], pt[sB][2]);
        D02[sD][sC] = d2s(pt[sD][0], pt[sC][2]);
        D02[sD][sD] = d2s(pt[sD][0], pt[sD][2]);
        D02[sB][sD] = d2s(pt[sB][0], pt[sD][2]);
        D02[sC][sD] = d2s(pt[sC][0], pt[sD][2]);
        sd2[sB]     = d2s(pt[sB][0], pt[sD][0]);
        sd1[sC]     = d2s(pt[sC][0], pt[sD][0]);

        // ---- output hb (rows sB,sC,sD)
        const float Sb = fmaxf(fmaxf(sd1[sB], sd2[sB]), sd1[sC]);
        const float P01b = max9(D01[sB][sB], D01[sB][sC], D01[sC][sB],
                                D01[sC][sC], D01[sD][sB], D01[sD][sC],
                                D01[sD][sD], D01[sB][sD], D01[sC][sD]);
        const float P02b = max9(D02[sB][sB], D02[sB][sC], D02[sC][sB],
                                D02[sC][sC], D02[sD][sB], D02[sD][sC],
                                D02[sD][sD], D02[sB][sD], D02[sC][sD]);

        const float S1b = __shfl_down_sync(FULLMASK, Sb,   1);
        const float S2b = __shfl_down_sync(FULLMASK, Sb,   2);
        const float Qb  = __shfl_down_sync(FULLMASK, P01b, 1);
        const float mb  = fmaxf(fmaxf(fmaxf(Sb, S1b), fmaxf(S2b, P01b)),
                                fmaxf(Qb, P02b));
        float vb;
        asm("sqrt.approx.f32 %0, %1;" : "=f"(vb) : "f"(mb));
        {
            const bool border = (hb == HD - 1) || (w_out == WD - 1);
            if (wvalid)
                out[((long)b * HD + hb) * WD + w_out] = border ? 0.0f : vb;
            if (zerocol)
                out[((long)b * HD + hb) * WD] = 0.0f;
        }
        // carried into next iter: rows sC,sD; D01/D02 over {sC,sD}; sd1[sC]
    }
}

extern "C" void kernel_launch(void* const* d_in, const int* in_sizes, int n_in,
                              void* d_out, int out_size)
{
    const float* x = (const float*)d_in[0];
    float* out = (float*)d_out;

    dim3 block(256, 1, 1);
    dim3 grid(1, HD / 8, 32);   // 28 row-tiles x 32 batches = 896 blocks
    maxlocaldist_kernel<<<grid, block>>>(x, out);
}